// round 14
// baseline (speedup 1.0000x reference)
#include <cuda_runtime.h>

// SplashEncoding — round 13.
// Base: R8 (107.3, best). R12 lesson: Morton sort only helps LINEAR levels
// 0-3 (hashed levels >= res 74 have <1 pt/cell -> no wavefront merging
// possible), and its 4 serial launches cost ~12us of critical-path latency.
// Restructure:
//   main:     repack_hash -> levels4_13 (original coords, no sort dep)
//   stream A: memset bins -> hist -> scan -> scatter -> repack_linear
//             -> lvl0_3 over SORTED points (the only sort beneficiary);
//             entire chain (~15us) hides under main's ~50us.
//   stream B: repack_splash -> splash (unchanged).
//
// Output layout: d_out = [feats (N,32) row-major][gmm (N,2) row-major].

#define HENTRIES 131072
#define HPAIRS   65536
#define NBINS    4096
#define MAXN     262144

#define MAGIC_I 0x4B000000u
#define MAGIC_F 8388608.0f
#define KQ   (1.0f / 131070.0f)
#define KF   (0.125f / 65535.0f)
#define KINV (1.0f / 1024.0f)
#define INV_SQRT2PI 0.3989422804014327f

// Splash tables
__device__ uint4 g_pair14[HPAIRS * 3];
__device__ uint4 g_pack15[HENTRIES * 3];

// Linear-level paired-x tables
__device__ float4 g_lin0[4096];
__device__ float4 g_lin1[12167];
__device__ float4 g_lin2[39304];
__device__ float4 g_lin3[125000];

// Hashed-level aligned-pair tables (tier 0): 10 x 65536 float4 = 10MB.
__device__ float4 g_hashp[10 * HPAIRS];

// Sort scratch
__device__ unsigned g_binCnt[NBINS];
__device__ unsigned g_binOff[NBINS];
__device__ uint4    g_sorted[MAXN];

__constant__ int FBH_C[10] = {180567,311639,442711,573783,704855,
                              835927,966999,1098071,1229143,1360215};

__device__ __forceinline__ unsigned int hash_yz(int iy, int iz) {
    return ((unsigned int)iy * 2654435761u) ^ ((unsigned int)iz * 805459861u);
}

__device__ __forceinline__ unsigned spread4(unsigned v) {
    return (v & 1u) | ((v & 2u) << 2) | ((v & 4u) << 4) | ((v & 8u) << 6);
}
__device__ __forceinline__ unsigned morton_bin(float cx, float cy, float cz) {
    int mx = (int)(cx * 16.0f), my = (int)(cy * 16.0f), mz = (int)(cz * 16.0f);
    mx = max(0, min(15, mx)); my = max(0, min(15, my)); mz = max(0, min(15, mz));
    return (spread4((unsigned)mx) << 2) | (spread4((unsigned)my) << 1) | spread4((unsigned)mz);
}

struct Cell {
    int px, py, pz;
    float wx0, wx1, wy0, wy1, wz0, wz1;
};

__device__ __forceinline__ Cell make_cell(float cx, float cy, float cz, int res, float ub) {
    Cell c;
    float x = fminf(fmaxf((float)res * cx, 0.0f), ub);
    float y = fminf(fmaxf((float)res * cy, 0.0f), ub);
    float z = fminf(fmaxf((float)res * cz, 0.0f), ub);
    c.px = (int)x; c.py = (int)y; c.pz = (int)z;
    float fx = x - (float)c.px, fy = y - (float)c.py, fz = z - (float)c.pz;
    c.wx0 = 1.0f - fx; c.wx1 = fx;
    c.wy0 = 1.0f - fy; c.wy1 = fy;
    c.wz0 = 1.0f - fz; c.wz1 = fz;
    return c;
}

__device__ __forceinline__ float dec_lo(unsigned int w) {
    return __uint_as_float(__byte_perm(w, MAGIC_I, 0x7410)) - MAGIC_F;
}
__device__ __forceinline__ float dec_hi(unsigned int w) {
    return __uint_as_float(__byte_perm(w, MAGIC_I, 0x7432)) - MAGIC_F;
}

__device__ __forceinline__ void gauss_q(
    unsigned int wa, unsigned int wb, unsigned int wf,
    float cxo, float cyo, float czo, float w,
    float& a0, float& a1, float& g)
{
    float dx  = fmaf(dec_lo(wa), -KQ, cxo);
    float dy  = fmaf(dec_hi(wa), -KQ, cyo);
    float dz  = fmaf(dec_lo(wb), -KQ, czo);
    float inv = dec_hi(wb) * KINV;
    float f0  = fmaf(dec_lo(wf), KF, -0.0625f);
    float f1  = fmaf(dec_hi(wf), KF, -0.0625f);

    float ss   = dx*dx + dy*dy + dz*dz;
    float inv2 = inv * inv;
    float sq   = 0.5f * ss * inv2;
    float gw   = __expf(-sq) * (inv * INV_SQRT2PI);
    float wg   = w * gw;
    a0 += wg * f0;
    a1 += wg * f1;
    g   = fmaf(wg * sq, 2.0f, g);
}

// ---------------------------------------------------------------------------
// Sort kernels (stream A)
// ---------------------------------------------------------------------------
__global__ __launch_bounds__(256)
void hist_kernel(const float* __restrict__ coords, int N)
{
    int n = blockIdx.x * 256 + threadIdx.x;
    if (n >= N) return;
    unsigned b = morton_bin(coords[3*n], coords[3*n+1], coords[3*n+2]);
    atomicAdd(&g_binCnt[b], 1u);
}

__global__ __launch_bounds__(256)
void scan_kernel()
{
    __shared__ unsigned ssum[256];
    int t = threadIdx.x;
    unsigned loc[16];
    unsigned s = 0;
    #pragma unroll
    for (int i = 0; i < 16; ++i) {
        loc[i] = s;
        s += g_binCnt[t * 16 + i];
    }
    ssum[t] = s;
    __syncthreads();
    for (int off = 1; off < 256; off <<= 1) {
        unsigned v = (t >= off) ? ssum[t - off] : 0u;
        __syncthreads();
        ssum[t] += v;
        __syncthreads();
    }
    unsigned pre = ssum[t] - s;
    #pragma unroll
    for (int i = 0; i < 16; ++i)
        g_binOff[t * 16 + i] = pre + loc[i];
}

__global__ __launch_bounds__(256)
void scatter_kernel(const float* __restrict__ coords, int N)
{
    int n = blockIdx.x * 256 + threadIdx.x;
    if (n >= N) return;
    float cx = coords[3*n], cy = coords[3*n+1], cz = coords[3*n+2];
    unsigned b = morton_bin(cx, cy, cz);
    unsigned pos = atomicAdd(&g_binOff[b], 1u);
    if (pos < MAXN)
        g_sorted[pos] = make_uint4(__float_as_uint(cx), __float_as_uint(cy),
                                   __float_as_uint(cz), (unsigned)n);
}

// ---------------------------------------------------------------------------
// Repack: hashed pair tables (main stream).
// ---------------------------------------------------------------------------
__global__ __launch_bounds__(256)
void repack_hash(const float* __restrict__ feats)
{
    unsigned g = blockIdx.x * 256u + threadIdx.x;
    if (g >= 10u * HPAIRS) return;
    unsigned l = g >> 16;
    unsigned i = g & 65535u;
    const float* p = feats + 2u * (unsigned)FBH_C[l] + 4u * i;
    float2 a = *(const float2*)(p + 0);
    float2 b = *(const float2*)(p + 2);
    g_hashp[l * HPAIRS + i] = make_float4(a.x, a.y, b.x, b.y);
}

// Repack: linear-level paired-x tables (stream A).
__global__ __launch_bounds__(256)
void repack_linear(const float* __restrict__ feats)
{
    int i = blockIdx.x * blockDim.x + threadIdx.x;
    if (i < 4096) {
        float2 a = *(const float2*)(feats + 2*i);
        float2 b = (i + 1 < 4096) ? *(const float2*)(feats + 2*i + 2) : a;
        g_lin0[i] = make_float4(a.x, a.y, b.x, b.y);
    }
    if (i < 12167) {
        const float* p = feats + 8192;
        float2 a = *(const float2*)(p + 2*i);
        float2 b = (i + 1 < 12167) ? *(const float2*)(p + 2*i + 2) : a;
        g_lin1[i] = make_float4(a.x, a.y, b.x, b.y);
    }
    if (i < 39304) {
        const float* p = feats + 32526;
        float2 a = *(const float2*)(p + 2*i);
        float2 b = (i + 1 < 39304) ? *(const float2*)(p + 2*i + 2) : a;
        g_lin2[i] = make_float4(a.x, a.y, b.x, b.y);
    }
    if (i < 125000) {
        const float* p = feats + 111134;
        float2 a = *(const float2*)(p + 2*i);
        float2 b = (i + 1 < 125000) ? *(const float2*)(p + 2*i + 2) : a;
        g_lin3[i] = make_float4(a.x, a.y, b.x, b.y);
    }
}

// ---------------------------------------------------------------------------
__device__ __forceinline__ unsigned int q16(float x, float off, float scale) {
    float v = fminf(fmaxf((x - off) * scale, 0.0f), 65535.0f);
    return __float2uint_rn(v);
}
__device__ __forceinline__ unsigned int qinv(float s) {
    float a = fabsf(s);
    float inv = 1.0f / fmaxf(a, 1.0f / 65535.0f);
    return __float2uint_rn(fminf(inv * 1024.0f, 65535.0f));
}
__device__ __forceinline__ unsigned int pack2(unsigned int lo, unsigned int hi) {
    return lo | (hi << 16);
}

__global__ __launch_bounds__(256)
void repack_splash(const float* __restrict__ feats,
                   const float* __restrict__ means,
                   const float* __restrict__ stds)
{
    unsigned g = blockIdx.x * 256u + threadIdx.x;
    const float FSC = 65535.0f / 0.125f;
    const float MSC = 131070.0f;

    if (g < HPAIRS) {
        size_t i = g;
        const float4* m4 = (const float4*)(means) + 3 * i;
        float4 M0 = m4[0], M1 = m4[1], M2 = m4[2];
        float4 S  = *((const float4*)(stds) + i);
        const float2* f2 = (const float2*)(feats + 2982574) + 4 * i;
        float2 F0 = f2[0], F1 = f2[1], F2 = f2[2], F3 = f2[3];

        uint4 A0, A1, FF;
        A0.x = pack2(q16(M0.x, 0.25f, MSC), q16(M0.y, 0.25f, MSC));
        A0.y = pack2(q16(M0.z, 0.25f, MSC), qinv(S.x));
        A0.z = pack2(q16(M0.w, 0.25f, MSC), q16(M1.x, 0.25f, MSC));
        A0.w = pack2(q16(M1.y, 0.25f, MSC), qinv(S.y));
        A1.x = pack2(q16(M1.z, 0.25f, MSC), q16(M1.w, 0.25f, MSC));
        A1.y = pack2(q16(M2.x, 0.25f, MSC), qinv(S.z));
        A1.z = pack2(q16(M2.y, 0.25f, MSC), q16(M2.z, 0.25f, MSC));
        A1.w = pack2(q16(M2.w, 0.25f, MSC), qinv(S.w));
        FF.x = pack2(q16(F0.x, -0.0625f, FSC), q16(F0.y, -0.0625f, FSC));
        FF.y = pack2(q16(F1.x, -0.0625f, FSC), q16(F1.y, -0.0625f, FSC));
        FF.z = pack2(q16(F2.x, -0.0625f, FSC), q16(F2.y, -0.0625f, FSC));
        FF.w = pack2(q16(F3.x, -0.0625f, FSC), q16(F3.y, -0.0625f, FSC));
        g_pair14[3 * i + 0] = A0;
        g_pair14[3 * i + 1] = A1;
        g_pair14[3 * i + 2] = FF;
    } else if (g < HPAIRS + HENTRIES) {
        size_t i = g - HPAIRS;
        const float4* m4 = (const float4*)(means + 786432) + 3 * i;
        float4 M0 = m4[0], M1 = m4[1], M2 = m4[2];
        float4 S  = *((const float4*)(stds + 262144) + i);
        const float2* f2 = (const float2*)(feats + 3506862) + 4 * i;
        float2 F0 = f2[0], F1 = f2[1], F2 = f2[2], F3 = f2[3];

        uint4 A, B, C;
        A.x = pack2(q16(M0.x, 0.25f, MSC), q16(M0.y, 0.25f, MSC));
        A.y = pack2(q16(M0.z, 0.25f, MSC), qinv(S.x));
        A.z = pack2(q16(M0.w, 0.25f, MSC), q16(M1.x, 0.25f, MSC));
        A.w = pack2(q16(M1.y, 0.25f, MSC), qinv(S.y));
        B.x = pack2(q16(M1.z, 0.25f, MSC), q16(M1.w, 0.25f, MSC));
        B.y = pack2(q16(M2.x, 0.25f, MSC), qinv(S.z));
        B.z = pack2(q16(M2.y, 0.25f, MSC), q16(M2.z, 0.25f, MSC));
        B.w = pack2(q16(M2.w, 0.25f, MSC), qinv(S.w));
        C.x = pack2(q16(F0.x, -0.0625f, FSC), q16(F0.y, -0.0625f, FSC));
        C.y = pack2(q16(F1.x, -0.0625f, FSC), q16(F1.y, -0.0625f, FSC));
        C.z = pack2(q16(F2.x, -0.0625f, FSC), q16(F2.y, -0.0625f, FSC));
        C.w = pack2(q16(F3.x, -0.0625f, FSC), q16(F3.y, -0.0625f, FSC));
        g_pack15[3 * i + 0] = A;
        g_pack15[3 * i + 1] = B;
        g_pack15[3 * i + 2] = C;
    }
}

// ---------------------------------------------------------------------------
// Levels 4..13 (original coords; order-indifferent).
// ---------------------------------------------------------------------------
__global__ __launch_bounds__(256)
void levels4_13_kernel(const float* __restrict__ coords,
                       float* __restrict__ out, int N)
{
    int n = blockIdx.x * blockDim.x + threadIdx.x;
    if (n >= N) return;

    float cx = coords[3*n + 0];
    float cy = coords[3*n + 1];
    float cz = coords[3*n + 2];

    float4* o4 = (float4*)(out + (size_t)n * 32);
    float pend0 = 0.0f, pend1 = 0.0f;

    constexpr int RESH[10] = {74,109,161,237,348,512,753,1108,1629,2394};
    #pragma unroll
    for (int h = 0; h < 10; ++h) {
        const int res = RESH[h];
        const float ub = (float)((double)res - 1.001);
        Cell c = make_cell(cx, cy, cz, res, ub);
        const float wy[2] = {c.wy0, c.wy1};
        const float wz[2] = {c.wz0, c.wz1};
        const float4* base4 = g_hashp + h * HPAIRS;
        const float2* base2 = (const float2*)base4;
        float a0 = 0.0f, a1 = 0.0f;
        const unsigned upx = (unsigned)c.px;
        const bool even = (c.px & 1) == 0;
        #pragma unroll
        for (int k = 0; k < 4; ++k) {
            const int oy = (k >> 1) & 1, oz = k & 1;
            unsigned t = hash_yz(c.py + oy, c.pz + oz);
            float wyz = wy[oy] * wz[oz];
            float v00, v01, v10, v11;
            if (even) {
                unsigned h0 = (upx ^ t) & 131071u;
                float4 P = base4[h0 >> 1];
                bool sw = (h0 & 1u) != 0u;
                v00 = sw ? P.z : P.x;  v01 = sw ? P.w : P.y;
                v10 = sw ? P.x : P.z;  v11 = sw ? P.y : P.w;
            } else {
                unsigned h0 = (upx ^ t) & 131071u;
                unsigned h1 = ((upx + 1u) ^ t) & 131071u;
                float2 fa = base2[h0];
                float2 fb = base2[h1];
                v00 = fa.x; v01 = fa.y; v10 = fb.x; v11 = fb.y;
            }
            a0 += wyz * (c.wx0 * v00 + c.wx1 * v10);
            a1 += wyz * (c.wx0 * v01 + c.wx1 * v11);
        }
        if ((h & 1) == 0) { pend0 = a0; pend1 = a1; }
        else o4[(h + 4) >> 1] = make_float4(pend0, pend1, a0, a1);
    }
}

// ---------------------------------------------------------------------------
// Levels 0..3 over SORTED points (sole sort beneficiary).
// ---------------------------------------------------------------------------
__global__ __launch_bounds__(256)
void lvl0_3_kernel(float* __restrict__ out, int N)
{
    int n = blockIdx.x * blockDim.x + threadIdx.x;
    if (n >= N) return;

    uint4 sp = g_sorted[n];
    float cx = __uint_as_float(sp.x);
    float cy = __uint_as_float(sp.y);
    float cz = __uint_as_float(sp.z);

    float4* o4 = (float4*)(out + (size_t)sp.w * 32);
    float pend0 = 0.0f, pend1 = 0.0f;

    constexpr int RESL[4] = {16, 23, 34, 50};
    #pragma unroll
    for (int lvl = 0; lvl < 4; ++lvl) {
        const int res = RESL[lvl];
        const float ub = (float)((double)res - 1.001);
        Cell c = make_cell(cx, cy, cz, res, ub);
        const float wy[2] = {c.wy0, c.wy1};
        const float wz[2] = {c.wz0, c.wz1};
        float a0 = 0.0f, a1 = 0.0f;
        #pragma unroll
        for (int k = 0; k < 4; ++k) {
            const int oy = (k >> 1) & 1, oz = k & 1;
            int idx = c.px + (c.py + oy) * res + (c.pz + oz) * res * res;
            float4 P;
            if (lvl == 0) P = g_lin0[idx];
            else if (lvl == 1) P = g_lin1[idx];
            else if (lvl == 2) P = g_lin2[idx];
            else P = g_lin3[idx];
            float wyz = wy[oy] * wz[oz];
            a0 += wyz * (c.wx0 * P.x + c.wx1 * P.z);
            a1 += wyz * (c.wx0 * P.y + c.wx1 * P.w);
        }
        if ((lvl & 1) == 0) { pend0 = a0; pend1 = a1; }
        else o4[lvl >> 1] = make_float4(pend0, pend1, a0, a1);
    }
}

// ---------------------------------------------------------------------------
// Splash levels 14/15 (identical to R8).
// ---------------------------------------------------------------------------
__global__ __launch_bounds__(256)
void splash_kernel(const float* __restrict__ coords,
                   float* __restrict__ out, int N)
{
    int n = blockIdx.x * blockDim.x + threadIdx.x;
    if (n >= N) return;

    float cx = coords[3*n + 0];
    float cy = coords[3*n + 1];
    float cz = coords[3*n + 2];
    float cxo = cx - 0.25f, cyo = cy - 0.25f, czo = cz - 0.25f;

    float r14_0 = 0.0f, r14_1 = 0.0f, g14 = 0.0f;
    float r15_0 = 0.0f, r15_1 = 0.0f, g15 = 0.0f;

    {
        Cell c = make_cell(cx, cy, cz, 3520, (float)(3520.0 - 1.001));
        const float wy[2] = {c.wy0, c.wy1};
        const float wz[2] = {c.wz0, c.wz1};
        const unsigned upx = (unsigned)c.px;
        const bool even = (c.px & 1) == 0;
        #pragma unroll
        for (int k = 0; k < 4; ++k) {
            const int oy = (k >> 1) & 1, oz = k & 1;
            unsigned tt = hash_yz(c.py + oy, c.pz + oz);
            float wyz = wy[oy] * wz[oz];
            float w0 = c.wx0 * wyz;
            float w1 = c.wx1 * wyz;
            if (even) {
                unsigned h0 = (upx ^ tt) & 131071u;
                unsigned j3 = (h0 >> 1) * 3u;
                uint4 R0 = g_pair14[j3 + 0];
                uint4 R1 = g_pair14[j3 + 1];
                uint4 FF = g_pair14[j3 + 2];
                bool sw = (h0 & 1u) != 0u;
                float wA = sw ? w1 : w0;
                float wB = sw ? w0 : w1;
                gauss_q(R0.x, R0.y, FF.x, cxo, cyo, czo, wA, r14_0, r14_1, g14);
                gauss_q(R0.z, R0.w, FF.y, cxo, cyo, czo, wA, r14_0, r14_1, g14);
                gauss_q(R1.x, R1.y, FF.z, cxo, cyo, czo, wB, r14_0, r14_1, g14);
                gauss_q(R1.z, R1.w, FF.w, cxo, cyo, czo, wB, r14_0, r14_1, g14);
            } else {
                #pragma unroll
                for (int ox = 0; ox < 2; ++ox) {
                    unsigned hh = ((upx + (unsigned)ox) ^ tt) & 131071u;
                    unsigned jb = (hh >> 1) * 3u;
                    uint4 A = g_pair14[jb + (hh & 1u)];
                    const uint2* f2p = (const uint2*)g_pair14;
                    uint2 F = f2p[(jb + 2u) * 2u + (hh & 1u)];
                    float w = ox ? w1 : w0;
                    gauss_q(A.x, A.y, F.x, cxo, cyo, czo, w, r14_0, r14_1, g14);
                    gauss_q(A.z, A.w, F.y, cxo, cyo, czo, w, r14_0, r14_1, g14);
                }
            }
        }
    }

    {
        Cell c = make_cell(cx, cy, cz, 5174, (float)(5174.0 - 1.001));
        const float wx[2] = {c.wx0, c.wx1};
        const float wy[2] = {c.wy0, c.wy1};
        const float wz[2] = {c.wz0, c.wz1};
        #pragma unroll
        for (int k = 0; k < 8; ++k) {
            const int ox = (k >> 2) & 1, oy = (k >> 1) & 1, oz = k & 1;
            unsigned idx = (((unsigned)(c.px + ox)) ^ hash_yz(c.py + oy, c.pz + oz)) & 131071u;
            float w = wx[ox] * wy[oy] * wz[oz];
            uint4 A = g_pack15[3 * (size_t)idx + 0];
            uint4 B = g_pack15[3 * (size_t)idx + 1];
            uint4 C = g_pack15[3 * (size_t)idx + 2];
            gauss_q(A.x, A.y, C.x, cxo, cyo, czo, w, r15_0, r15_1, g15);
            gauss_q(A.z, A.w, C.y, cxo, cyo, czo, w, r15_0, r15_1, g15);
            gauss_q(B.x, B.y, C.z, cxo, cyo, czo, w, r15_0, r15_1, g15);
            gauss_q(B.z, B.w, C.w, cxo, cyo, czo, w, r15_0, r15_1, g15);
        }
    }

    *(float4*)(out + (size_t)n * 32 + 28) = make_float4(r14_0, r14_1, r15_0, r15_1);
    *(float2*)(out + (size_t)N * 32 + 2 * (size_t)n) = make_float2(g14, g15);
}

extern "C" void kernel_launch(void* const* d_in, const int* in_sizes, int n_in,
                              void* d_out, int out_size)
{
    const float* coords = (const float*)d_in[0];
    const float* feats  = (const float*)d_in[1];
    const float* means  = (const float*)d_in[2];
    const float* stds   = (const float*)d_in[3];
    float* out = (float*)d_out;

    int N = in_sizes[0] / 3;
    const int threads = 256;
    const int nblk = (N + threads - 1) / threads;

    static cudaStream_t sA = nullptr, sB = nullptr;
    static cudaEvent_t evFork = nullptr, evA = nullptr, evB = nullptr;
    static void* binCntPtr = nullptr;
    if (sA == nullptr) {
        cudaStreamCreateWithFlags(&sA, cudaStreamNonBlocking);
        cudaStreamCreateWithFlags(&sB, cudaStreamNonBlocking);
        cudaEventCreateWithFlags(&evFork, cudaEventDisableTiming);
        cudaEventCreateWithFlags(&evA, cudaEventDisableTiming);
        cudaEventCreateWithFlags(&evB, cudaEventDisableTiming);
        cudaGetSymbolAddress(&binCntPtr, g_binCnt);
    }

    cudaEventRecord(evFork, 0);
    cudaStreamWaitEvent(sA, evFork, 0);
    cudaStreamWaitEvent(sB, evFork, 0);

    // Stream A: bin zero -> hist -> scan -> scatter -> linear repack -> lvl0_3.
    cudaMemsetAsync(binCntPtr, 0, NBINS * sizeof(unsigned), sA);
    hist_kernel<<<nblk, threads, 0, sA>>>(coords, N);
    scan_kernel<<<1, 256, 0, sA>>>();
    scatter_kernel<<<nblk, threads, 0, sA>>>(coords, N);
    repack_linear<<<(125000 + threads - 1) / threads, threads, 0, sA>>>(feats);
    lvl0_3_kernel<<<nblk, threads, 0, sA>>>(out, N);
    cudaEventRecord(evA, sA);

    // Stream B: splash repack -> splash.
    repack_splash<<<(HPAIRS + HENTRIES + threads - 1) / threads, threads, 0, sB>>>(feats, means, stds);
    splash_kernel<<<nblk, threads, 0, sB>>>(coords, out, N);
    cudaEventRecord(evB, sB);

    // Main stream: hash-pair repack, then the big hashed-levels kernel.
    repack_hash<<<(10 * HPAIRS + threads - 1) / threads, threads>>>(feats);
    levels4_13_kernel<<<nblk, threads>>>(coords, out, N);

    cudaStreamWaitEvent(0, evA, 0);
    cudaStreamWaitEvent(0, evB, 0);
}

// round 15
// speedup vs baseline: 1.0867x; 1.0867x over previous
#include <cuda_runtime.h>

// SplashEncoding — round 14 == exact R8 restore (verified best: 107.3us).
// Structure:
//   main:     repack_hash (flattened, 2560 blocks) -> levels4_13
//   stream A: repack_linear -> lvl0_3
//   stream B: repack_splash -> splash
// Techniques locked in: u16-quantized splash AoS (inv_s stored, 1 MUFU/gauss),
// even-x hash-pair LDG.128 loads (tier-0 only), paired-x linear tables,
// pair-packed lvl14, direct strided float4 stores.
// Closed directions (measured regressions): smem store staging (R7), tier>=1
// xor-block tables (R9/R10), kernel merging (R11), Morton sort (R12/R13).
//
// Output layout: d_out = [feats (N,32) row-major][gmm (N,2) row-major].

#define HENTRIES 131072
#define HPAIRS   65536

#define MAGIC_I 0x4B000000u
#define MAGIC_F 8388608.0f
#define KQ   (1.0f / 131070.0f)
#define KF   (0.125f / 65535.0f)
#define KINV (1.0f / 1024.0f)
#define INV_SQRT2PI 0.3989422804014327f

// Splash tables
__device__ uint4 g_pair14[HPAIRS * 3];     // pair j: [A(2j)][A(2j+1)][F(2j)|F(2j+1)]
__device__ uint4 g_pack15[HENTRIES * 3];   // entry i: [m0 i0 m1 i1][m2 i2 m3 i3][f0..f3]

// Linear-level paired-x tables
__device__ float4 g_lin0[4096];
__device__ float4 g_lin1[12167];
__device__ float4 g_lin2[39304];
__device__ float4 g_lin3[125000];

// Hashed-level aligned-pair tables
__device__ float4 g_hashp[10 * HPAIRS];

__constant__ int FBH_C[10] = {180567,311639,442711,573783,704855,
                              835927,966999,1098071,1229143,1360215};

__device__ __forceinline__ unsigned int hash_yz(int iy, int iz) {
    return ((unsigned int)iy * 2654435761u) ^ ((unsigned int)iz * 805459861u);
}

struct Cell {
    int px, py, pz;
    float wx0, wx1, wy0, wy1, wz0, wz1;
};

__device__ __forceinline__ Cell make_cell(float cx, float cy, float cz, int res, float ub) {
    Cell c;
    float x = fminf(fmaxf((float)res * cx, 0.0f), ub);
    float y = fminf(fmaxf((float)res * cy, 0.0f), ub);
    float z = fminf(fmaxf((float)res * cz, 0.0f), ub);
    c.px = (int)x; c.py = (int)y; c.pz = (int)z;
    float fx = x - (float)c.px, fy = y - (float)c.py, fz = z - (float)c.pz;
    c.wx0 = 1.0f - fx; c.wx1 = fx;
    c.wy0 = 1.0f - fy; c.wy1 = fy;
    c.wz0 = 1.0f - fz; c.wz1 = fz;
    return c;
}

__device__ __forceinline__ float dec_lo(unsigned int w) {
    return __uint_as_float(__byte_perm(w, MAGIC_I, 0x7410)) - MAGIC_F;
}
__device__ __forceinline__ float dec_hi(unsigned int w) {
    return __uint_as_float(__byte_perm(w, MAGIC_I, 0x7432)) - MAGIC_F;
}

__device__ __forceinline__ void gauss_q(
    unsigned int wa, unsigned int wb, unsigned int wf,
    float cxo, float cyo, float czo, float w,
    float& a0, float& a1, float& g)
{
    float dx  = fmaf(dec_lo(wa), -KQ, cxo);
    float dy  = fmaf(dec_hi(wa), -KQ, cyo);
    float dz  = fmaf(dec_lo(wb), -KQ, czo);
    float inv = dec_hi(wb) * KINV;
    float f0  = fmaf(dec_lo(wf), KF, -0.0625f);
    float f1  = fmaf(dec_hi(wf), KF, -0.0625f);

    float ss   = dx*dx + dy*dy + dz*dz;
    float inv2 = inv * inv;
    float sq   = 0.5f * ss * inv2;
    float gw   = __expf(-sq) * (inv * INV_SQRT2PI);
    float wg   = w * gw;
    a0 += wg * f0;
    a1 += wg * f1;
    g   = fmaf(wg * sq, 2.0f, g);
}

// ---------------------------------------------------------------------------
// Repack hashed tables: one (pair, level) per thread -> 2560 blocks.
// ---------------------------------------------------------------------------
__global__ __launch_bounds__(256)
void repack_hash(const float* __restrict__ feats)
{
    unsigned g = blockIdx.x * 256u + threadIdx.x;     // 0 .. 10*HPAIRS-1
    if (g >= 10u * HPAIRS) return;
    unsigned l = g >> 16;          // level 0..9
    unsigned i = g & 65535u;       // pair index
    const float* p = feats + 2u * (unsigned)FBH_C[l] + 4u * i;
    float2 a = *(const float2*)(p + 0);
    float2 b = *(const float2*)(p + 2);
    g_hashp[l * HPAIRS + i] = make_float4(a.x, a.y, b.x, b.y);
}

// ---------------------------------------------------------------------------
__global__ __launch_bounds__(256)
void repack_linear(const float* __restrict__ feats)
{
    int i = blockIdx.x * blockDim.x + threadIdx.x;
    if (i < 4096) {
        float2 a = *(const float2*)(feats + 2*i);
        float2 b = (i + 1 < 4096) ? *(const float2*)(feats + 2*i + 2) : a;
        g_lin0[i] = make_float4(a.x, a.y, b.x, b.y);
    }
    if (i < 12167) {
        const float* p = feats + 8192;
        float2 a = *(const float2*)(p + 2*i);
        float2 b = (i + 1 < 12167) ? *(const float2*)(p + 2*i + 2) : a;
        g_lin1[i] = make_float4(a.x, a.y, b.x, b.y);
    }
    if (i < 39304) {
        const float* p = feats + 32526;
        float2 a = *(const float2*)(p + 2*i);
        float2 b = (i + 1 < 39304) ? *(const float2*)(p + 2*i + 2) : a;
        g_lin2[i] = make_float4(a.x, a.y, b.x, b.y);
    }
    if (i < 125000) {
        const float* p = feats + 111134;
        float2 a = *(const float2*)(p + 2*i);
        float2 b = (i + 1 < 125000) ? *(const float2*)(p + 2*i + 2) : a;
        g_lin3[i] = make_float4(a.x, a.y, b.x, b.y);
    }
}

// ---------------------------------------------------------------------------
__device__ __forceinline__ unsigned int q16(float x, float off, float scale) {
    float v = fminf(fmaxf((x - off) * scale, 0.0f), 65535.0f);
    return __float2uint_rn(v);
}
__device__ __forceinline__ unsigned int qinv(float s) {
    float a = fabsf(s);
    float inv = 1.0f / fmaxf(a, 1.0f / 65535.0f);
    return __float2uint_rn(fminf(inv * 1024.0f, 65535.0f));
}
__device__ __forceinline__ unsigned int pack2(unsigned int lo, unsigned int hi) {
    return lo | (hi << 16);
}

// Disjoint ranges: g < HPAIRS -> level-14 pair; else level-15 entry.
__global__ __launch_bounds__(256)
void repack_splash(const float* __restrict__ feats,
                   const float* __restrict__ means,
                   const float* __restrict__ stds)
{
    unsigned g = blockIdx.x * 256u + threadIdx.x;
    const float FSC = 65535.0f / 0.125f;
    const float MSC = 131070.0f;

    if (g < HPAIRS) {
        size_t i = g;
        const float4* m4 = (const float4*)(means) + 3 * i;
        float4 M0 = m4[0], M1 = m4[1], M2 = m4[2];
        float4 S  = *((const float4*)(stds) + i);
        const float2* f2 = (const float2*)(feats + 2982574) + 4 * i;
        float2 F0 = f2[0], F1 = f2[1], F2 = f2[2], F3 = f2[3];

        uint4 A0, A1, FF;
        A0.x = pack2(q16(M0.x, 0.25f, MSC), q16(M0.y, 0.25f, MSC));
        A0.y = pack2(q16(M0.z, 0.25f, MSC), qinv(S.x));
        A0.z = pack2(q16(M0.w, 0.25f, MSC), q16(M1.x, 0.25f, MSC));
        A0.w = pack2(q16(M1.y, 0.25f, MSC), qinv(S.y));
        A1.x = pack2(q16(M1.z, 0.25f, MSC), q16(M1.w, 0.25f, MSC));
        A1.y = pack2(q16(M2.x, 0.25f, MSC), qinv(S.z));
        A1.z = pack2(q16(M2.y, 0.25f, MSC), q16(M2.z, 0.25f, MSC));
        A1.w = pack2(q16(M2.w, 0.25f, MSC), qinv(S.w));
        FF.x = pack2(q16(F0.x, -0.0625f, FSC), q16(F0.y, -0.0625f, FSC));
        FF.y = pack2(q16(F1.x, -0.0625f, FSC), q16(F1.y, -0.0625f, FSC));
        FF.z = pack2(q16(F2.x, -0.0625f, FSC), q16(F2.y, -0.0625f, FSC));
        FF.w = pack2(q16(F3.x, -0.0625f, FSC), q16(F3.y, -0.0625f, FSC));
        g_pair14[3 * i + 0] = A0;
        g_pair14[3 * i + 1] = A1;
        g_pair14[3 * i + 2] = FF;
    } else if (g < HPAIRS + HENTRIES) {
        size_t i = g - HPAIRS;
        const float4* m4 = (const float4*)(means + 786432) + 3 * i;
        float4 M0 = m4[0], M1 = m4[1], M2 = m4[2];
        float4 S  = *((const float4*)(stds + 262144) + i);
        const float2* f2 = (const float2*)(feats + 3506862) + 4 * i;
        float2 F0 = f2[0], F1 = f2[1], F2 = f2[2], F3 = f2[3];

        uint4 A, B, C;
        A.x = pack2(q16(M0.x, 0.25f, MSC), q16(M0.y, 0.25f, MSC));
        A.y = pack2(q16(M0.z, 0.25f, MSC), qinv(S.x));
        A.z = pack2(q16(M0.w, 0.25f, MSC), q16(M1.x, 0.25f, MSC));
        A.w = pack2(q16(M1.y, 0.25f, MSC), qinv(S.y));
        B.x = pack2(q16(M1.z, 0.25f, MSC), q16(M1.w, 0.25f, MSC));
        B.y = pack2(q16(M2.x, 0.25f, MSC), qinv(S.z));
        B.z = pack2(q16(M2.y, 0.25f, MSC), q16(M2.z, 0.25f, MSC));
        B.w = pack2(q16(M2.w, 0.25f, MSC), qinv(S.w));
        C.x = pack2(q16(F0.x, -0.0625f, FSC), q16(F0.y, -0.0625f, FSC));
        C.y = pack2(q16(F1.x, -0.0625f, FSC), q16(F1.y, -0.0625f, FSC));
        C.z = pack2(q16(F2.x, -0.0625f, FSC), q16(F2.y, -0.0625f, FSC));
        C.w = pack2(q16(F3.x, -0.0625f, FSC), q16(F3.y, -0.0625f, FSC));
        g_pack15[3 * i + 0] = A;
        g_pack15[3 * i + 1] = B;
        g_pack15[3 * i + 2] = C;
    }
}

// ---------------------------------------------------------------------------
// Levels 4..13: hashed gathers with even-x pair loads. Direct strided stores.
// ---------------------------------------------------------------------------
__global__ __launch_bounds__(256)
void levels4_13_kernel(const float* __restrict__ coords,
                       float* __restrict__ out, int N)
{
    int n = blockIdx.x * blockDim.x + threadIdx.x;
    if (n >= N) return;

    float cx = coords[3*n + 0];
    float cy = coords[3*n + 1];
    float cz = coords[3*n + 2];

    float4* o4 = (float4*)(out + (size_t)n * 32);
    float pend0 = 0.0f, pend1 = 0.0f;

    constexpr int RESH[10] = {74,109,161,237,348,512,753,1108,1629,2394};
    #pragma unroll
    for (int h = 0; h < 10; ++h) {
        const int res = RESH[h];
        const float ub = (float)((double)res - 1.001);
        Cell c = make_cell(cx, cy, cz, res, ub);
        const float wy[2] = {c.wy0, c.wy1};
        const float wz[2] = {c.wz0, c.wz1};
        const float4* base4 = g_hashp + h * HPAIRS;
        const float2* base2 = (const float2*)base4;
        float a0 = 0.0f, a1 = 0.0f;
        const unsigned upx = (unsigned)c.px;
        const bool even = (c.px & 1) == 0;
        #pragma unroll
        for (int k = 0; k < 4; ++k) {
            const int oy = (k >> 1) & 1, oz = k & 1;
            unsigned t = hash_yz(c.py + oy, c.pz + oz);
            float wyz = wy[oy] * wz[oz];
            float v00, v01, v10, v11;
            if (even) {
                unsigned h0 = (upx ^ t) & 131071u;
                float4 P = base4[h0 >> 1];
                bool sw = (h0 & 1u) != 0u;
                v00 = sw ? P.z : P.x;  v01 = sw ? P.w : P.y;
                v10 = sw ? P.x : P.z;  v11 = sw ? P.y : P.w;
            } else {
                unsigned h0 = (upx ^ t) & 131071u;
                unsigned h1 = ((upx + 1u) ^ t) & 131071u;
                float2 fa = base2[h0];
                float2 fb = base2[h1];
                v00 = fa.x; v01 = fa.y; v10 = fb.x; v11 = fb.y;
            }
            a0 += wyz * (c.wx0 * v00 + c.wx1 * v10);
            a1 += wyz * (c.wx0 * v01 + c.wx1 * v11);
        }
        if ((h & 1) == 0) { pend0 = a0; pend1 = a1; }
        else o4[(h + 4) >> 1] = make_float4(pend0, pend1, a0, a1);
    }
}

// ---------------------------------------------------------------------------
__global__ __launch_bounds__(256)
void lvl0_3_kernel(const float* __restrict__ coords,
                   float* __restrict__ out, int N)
{
    int n = blockIdx.x * blockDim.x + threadIdx.x;
    if (n >= N) return;

    float cx = coords[3*n + 0];
    float cy = coords[3*n + 1];
    float cz = coords[3*n + 2];

    float4* o4 = (float4*)(out + (size_t)n * 32);
    float pend0 = 0.0f, pend1 = 0.0f;

    constexpr int RESL[4] = {16, 23, 34, 50};
    #pragma unroll
    for (int lvl = 0; lvl < 4; ++lvl) {
        const int res = RESL[lvl];
        const float ub = (float)((double)res - 1.001);
        Cell c = make_cell(cx, cy, cz, res, ub);
        const float wy[2] = {c.wy0, c.wy1};
        const float wz[2] = {c.wz0, c.wz1};
        float a0 = 0.0f, a1 = 0.0f;
        #pragma unroll
        for (int k = 0; k < 4; ++k) {
            const int oy = (k >> 1) & 1, oz = k & 1;
            int idx = c.px + (c.py + oy) * res + (c.pz + oz) * res * res;
            float4 P;
            if (lvl == 0) P = g_lin0[idx];
            else if (lvl == 1) P = g_lin1[idx];
            else if (lvl == 2) P = g_lin2[idx];
            else P = g_lin3[idx];
            float wyz = wy[oy] * wz[oz];
            a0 += wyz * (c.wx0 * P.x + c.wx1 * P.z);
            a1 += wyz * (c.wx0 * P.y + c.wx1 * P.w);
        }
        if ((lvl & 1) == 0) { pend0 = a0; pend1 = a1; }
        else o4[lvl >> 1] = make_float4(pend0, pend1, a0, a1);
    }
}

// ---------------------------------------------------------------------------
// Splash levels 14/15.
// ---------------------------------------------------------------------------
__global__ __launch_bounds__(256)
void splash_kernel(const float* __restrict__ coords,
                   float* __restrict__ out, int N)
{
    int n = blockIdx.x * blockDim.x + threadIdx.x;
    if (n >= N) return;

    float cx = coords[3*n + 0];
    float cy = coords[3*n + 1];
    float cz = coords[3*n + 2];
    float cxo = cx - 0.25f, cyo = cy - 0.25f, czo = cz - 0.25f;

    float r14_0 = 0.0f, r14_1 = 0.0f, g14 = 0.0f;
    float r15_0 = 0.0f, r15_1 = 0.0f, g15 = 0.0f;

    // ----- level 14: res=3520, ns=2, pair-packed -----
    {
        Cell c = make_cell(cx, cy, cz, 3520, (float)(3520.0 - 1.001));
        const float wy[2] = {c.wy0, c.wy1};
        const float wz[2] = {c.wz0, c.wz1};
        const unsigned upx = (unsigned)c.px;
        const bool even = (c.px & 1) == 0;
        #pragma unroll
        for (int k = 0; k < 4; ++k) {
            const int oy = (k >> 1) & 1, oz = k & 1;
            unsigned tt = hash_yz(c.py + oy, c.pz + oz);
            float wyz = wy[oy] * wz[oz];
            float w0 = c.wx0 * wyz;
            float w1 = c.wx1 * wyz;
            if (even) {
                unsigned h0 = (upx ^ tt) & 131071u;
                unsigned j3 = (h0 >> 1) * 3u;
                uint4 R0 = g_pair14[j3 + 0];
                uint4 R1 = g_pair14[j3 + 1];
                uint4 FF = g_pair14[j3 + 2];
                bool sw = (h0 & 1u) != 0u;
                float wA = sw ? w1 : w0;
                float wB = sw ? w0 : w1;
                gauss_q(R0.x, R0.y, FF.x, cxo, cyo, czo, wA, r14_0, r14_1, g14);
                gauss_q(R0.z, R0.w, FF.y, cxo, cyo, czo, wA, r14_0, r14_1, g14);
                gauss_q(R1.x, R1.y, FF.z, cxo, cyo, czo, wB, r14_0, r14_1, g14);
                gauss_q(R1.z, R1.w, FF.w, cxo, cyo, czo, wB, r14_0, r14_1, g14);
            } else {
                #pragma unroll
                for (int ox = 0; ox < 2; ++ox) {
                    unsigned hh = ((upx + (unsigned)ox) ^ tt) & 131071u;
                    unsigned jb = (hh >> 1) * 3u;
                    uint4 A = g_pair14[jb + (hh & 1u)];
                    const uint2* f2p = (const uint2*)g_pair14;
                    uint2 F = f2p[(jb + 2u) * 2u + (hh & 1u)];
                    float w = ox ? w1 : w0;
                    gauss_q(A.x, A.y, F.x, cxo, cyo, czo, w, r14_0, r14_1, g14);
                    gauss_q(A.z, A.w, F.y, cxo, cyo, czo, w, r14_0, r14_1, g14);
                }
            }
        }
    }

    // ----- level 15: res=5174, ns=4 -----
    {
        Cell c = make_cell(cx, cy, cz, 5174, (float)(5174.0 - 1.001));
        const float wx[2] = {c.wx0, c.wx1};
        const float wy[2] = {c.wy0, c.wy1};
        const float wz[2] = {c.wz0, c.wz1};
        #pragma unroll
        for (int k = 0; k < 8; ++k) {
            const int ox = (k >> 2) & 1, oy = (k >> 1) & 1, oz = k & 1;
            unsigned idx = (((unsigned)(c.px + ox)) ^ hash_yz(c.py + oy, c.pz + oz)) & 131071u;
            float w = wx[ox] * wy[oy] * wz[oz];
            uint4 A = g_pack15[3 * (size_t)idx + 0];
            uint4 B = g_pack15[3 * (size_t)idx + 1];
            uint4 C = g_pack15[3 * (size_t)idx + 2];
            gauss_q(A.x, A.y, C.x, cxo, cyo, czo, w, r15_0, r15_1, g15);
            gauss_q(A.z, A.w, C.y, cxo, cyo, czo, w, r15_0, r15_1, g15);
            gauss_q(B.x, B.y, C.z, cxo, cyo, czo, w, r15_0, r15_1, g15);
            gauss_q(B.z, B.w, C.w, cxo, cyo, czo, w, r15_0, r15_1, g15);
        }
    }

    *(float4*)(out + (size_t)n * 32 + 28) = make_float4(r14_0, r14_1, r15_0, r15_1);
    *(float2*)(out + (size_t)N * 32 + 2 * (size_t)n) = make_float2(g14, g15);
}

extern "C" void kernel_launch(void* const* d_in, const int* in_sizes, int n_in,
                              void* d_out, int out_size)
{
    const float* coords = (const float*)d_in[0];
    const float* feats  = (const float*)d_in[1];
    const float* means  = (const float*)d_in[2];
    const float* stds   = (const float*)d_in[3];
    float* out = (float*)d_out;

    int N = in_sizes[0] / 3;
    const int threads = 256;
    const int nblk = (N + threads - 1) / threads;

    static cudaStream_t sA = nullptr, sB = nullptr;
    static cudaEvent_t evFork = nullptr, evA = nullptr, evB = nullptr;
    if (sA == nullptr) {
        cudaStreamCreateWithFlags(&sA, cudaStreamNonBlocking);
        cudaStreamCreateWithFlags(&sB, cudaStreamNonBlocking);
        cudaEventCreateWithFlags(&evFork, cudaEventDisableTiming);
        cudaEventCreateWithFlags(&evA, cudaEventDisableTiming);
        cudaEventCreateWithFlags(&evB, cudaEventDisableTiming);
    }

    cudaEventRecord(evFork, 0);
    cudaStreamWaitEvent(sA, evFork, 0);
    cudaStreamWaitEvent(sB, evFork, 0);

    // Stream A: linear repack -> levels 0-3
    repack_linear<<<(125000 + threads - 1) / threads, threads, 0, sA>>>(feats);
    lvl0_3_kernel<<<nblk, threads, 0, sA>>>(coords, out, N);
    cudaEventRecord(evA, sA);

    // Stream B: splash repack -> splash
    repack_splash<<<(HPAIRS + HENTRIES + threads - 1) / threads, threads, 0, sB>>>(feats, means, stds);
    splash_kernel<<<nblk, threads, 0, sB>>>(coords, out, N);
    cudaEventRecord(evB, sB);

    // Main stream: hash-table repack (flattened), then the hashed-levels kernel.
    repack_hash<<<(10 * HPAIRS + threads - 1) / threads, threads>>>(feats);
    levels4_13_kernel<<<nblk, threads>>>(coords, out, N);

    cudaStreamWaitEvent(0, evA, 0);
    cudaStreamWaitEvent(0, evB, 0);
}